// round 11
// baseline (speedup 1.0000x reference)
#include <cuda_runtime.h>
#include <cuda_bf16.h>

typedef unsigned long long ull;

// ---------------- problem constants ----------------
#define TT 512
#define BB 32
#define HH 512
#define GM 16384          // T*B
#define GN 4096           // 2 dirs * 4H
#define GK 512            // D (= H)

// ---------------- scratch ----------------
__device__ float g_xpre[(size_t)GM * GN];   // precomputed input gates (+ both biases)
__device__ unsigned int g_bar;              // grid barrier counter

// ---------------- f32x2 helpers ----------------
__device__ __forceinline__ ull pack2(float lo, float hi) {
    ull r; asm("mov.b64 %0, {%1, %2};" : "=l"(r) : "f"(lo), "f"(hi)); return r;
}
__device__ __forceinline__ void unpack2(ull v, float& lo, float& hi) {
    asm("mov.b64 {%0, %1}, %2;" : "=f"(lo), "=f"(hi) : "l"(v));
}
__device__ __forceinline__ ull fma2(ull a, ull b, ull c) {
    ull d; asm("fma.rn.f32x2 %0, %1, %2, %3;" : "=l"(d) : "l"(a), "l"(b), "l"(c)); return d;
}
__device__ __forceinline__ ull add2(ull a, ull b) {
    ull d; asm("add.rn.f32x2 %0, %1, %2;" : "=l"(d) : "l"(a), "l"(b)); return d;
}

// ============================================================
// Kernel 1: x_pre GEMM.  C[m][n] = A[m][:] . W[n][:] + bih[n] + bhh[n]
// A: [16384][512] (x), W: [4096][512] (W_ih both dirs), C -> g_xpre.
// 128x128x16 tiles, 256 threads, 8x8 per thread, f32x2 packed FMA,
// double-buffered smem.
// ============================================================
#define BM 128
#define BN 128
#define BK 16

__global__ void __launch_bounds__(256, 2) gemm_xpre(
    const float* __restrict__ A, const float* __restrict__ W,
    const float* __restrict__ bih, const float* __restrict__ bhh)
{
    if (blockIdx.x == 0 && blockIdx.y == 0 && threadIdx.x == 0) g_bar = 0;

    __shared__ float As[2][BK][BM];
    __shared__ float Bs[2][BK][BN];

    const int tid = threadIdx.x;
    const int m0 = blockIdx.y * BM;
    const int n0 = blockIdx.x * BN;

    // global-load mapping: 64 rows x 4 float4-columns per pass, 2 passes (128 rows)
    const int lr = tid >> 2;           // 0..63
    const int lk = (tid & 3) << 2;     // 0,4,8,12 (float offset within k-tile)
    const int lk4 = tid & 3;           // float4 offset within k-tile

    const float4* A4 = (const float4*)A;   // row stride = 128 float4
    const float4* W4 = (const float4*)W;

    // compute mapping
    const int ty = tid >> 4;   // 0..15 -> m
    const int tx = tid & 15;   // 0..15 -> n

    ull acc[8][4];
#pragma unroll
    for (int i = 0; i < 8; i++)
#pragma unroll
        for (int j = 0; j < 4; j++) acc[i][j] = 0ull;

    // prologue: tile 0 straight into buffer 0
    {
        int ak = lk4;  // kt=0
        float4 a0 = A4[(size_t)(m0 + lr) * 128 + ak];
        float4 a1 = A4[(size_t)(m0 + lr + 64) * 128 + ak];
        float4 b0 = W4[(size_t)(n0 + lr) * 128 + ak];
        float4 b1 = W4[(size_t)(n0 + lr + 64) * 128 + ak];
        As[0][lk + 0][lr] = a0.x; As[0][lk + 1][lr] = a0.y;
        As[0][lk + 2][lr] = a0.z; As[0][lk + 3][lr] = a0.w;
        As[0][lk + 0][lr + 64] = a1.x; As[0][lk + 1][lr + 64] = a1.y;
        As[0][lk + 2][lr + 64] = a1.z; As[0][lk + 3][lr + 64] = a1.w;
        Bs[0][lk + 0][lr] = b0.x; Bs[0][lk + 1][lr] = b0.y;
        Bs[0][lk + 2][lr] = b0.z; Bs[0][lk + 3][lr] = b0.w;
        Bs[0][lk + 0][lr + 64] = b1.x; Bs[0][lk + 1][lr + 64] = b1.y;
        Bs[0][lk + 2][lr + 64] = b1.z; Bs[0][lk + 3][lr + 64] = b1.w;
    }
    __syncthreads();

    int bf = 0;
    const int NKT = GK / BK;   // 32
    float4 ra0, ra1, rb0, rb1;

    for (int kt = 0; kt < NKT; kt++) {
        if (kt < NKT - 1) {
            int ak = (kt + 1) * 4 + lk4;
            ra0 = A4[(size_t)(m0 + lr) * 128 + ak];
            ra1 = A4[(size_t)(m0 + lr + 64) * 128 + ak];
            rb0 = W4[(size_t)(n0 + lr) * 128 + ak];
            rb1 = W4[(size_t)(n0 + lr + 64) * 128 + ak];
        }
#pragma unroll
        for (int k = 0; k < BK; k++) {
            float4 a0 = *(const float4*)&As[bf][k][ty * 8];
            float4 a1 = *(const float4*)&As[bf][k][ty * 8 + 4];
            ulonglong2 bA = *(const ulonglong2*)&Bs[bf][k][tx * 8];
            ulonglong2 bB = *(const ulonglong2*)&Bs[bf][k][tx * 8 + 4];
            ull bb0 = bA.x, bb1 = bA.y, bb2 = bB.x, bb3 = bB.y;
            float av[8] = {a0.x, a0.y, a0.z, a0.w, a1.x, a1.y, a1.z, a1.w};
#pragma unroll
            for (int i = 0; i < 8; i++) {
                ull ap = pack2(av[i], av[i]);
                acc[i][0] = fma2(ap, bb0, acc[i][0]);
                acc[i][1] = fma2(ap, bb1, acc[i][1]);
                acc[i][2] = fma2(ap, bb2, acc[i][2]);
                acc[i][3] = fma2(ap, bb3, acc[i][3]);
            }
        }
        if (kt < NKT - 1) {
            int nb = bf ^ 1;
            As[nb][lk + 0][lr] = ra0.x; As[nb][lk + 1][lr] = ra0.y;
            As[nb][lk + 2][lr] = ra0.z; As[nb][lk + 3][lr] = ra0.w;
            As[nb][lk + 0][lr + 64] = ra1.x; As[nb][lk + 1][lr + 64] = ra1.y;
            As[nb][lk + 2][lr + 64] = ra1.z; As[nb][lk + 3][lr + 64] = ra1.w;
            Bs[nb][lk + 0][lr] = rb0.x; Bs[nb][lk + 1][lr] = rb0.y;
            Bs[nb][lk + 2][lr] = rb0.z; Bs[nb][lk + 3][lr] = rb0.w;
            Bs[nb][lk + 0][lr + 64] = rb1.x; Bs[nb][lk + 1][lr + 64] = rb1.y;
            Bs[nb][lk + 2][lr + 64] = rb1.z; Bs[nb][lk + 3][lr + 64] = rb1.w;
            __syncthreads();
            bf = nb;
        }
    }

    // epilogue: add (b_ih + b_hh), store
    float bias[8];
#pragma unroll
    for (int j = 0; j < 8; j++) {
        int n = n0 + tx * 8 + j;
        bias[j] = bih[n] + bhh[n];
    }
#pragma unroll
    for (int i = 0; i < 8; i++) {
        size_t m = (size_t)(m0 + ty * 8 + i);
        float4 v0, v1;
        unpack2(acc[i][0], v0.x, v0.y);
        unpack2(acc[i][1], v0.z, v0.w);
        unpack2(acc[i][2], v1.x, v1.y);
        unpack2(acc[i][3], v1.z, v1.w);
        v0.x += bias[0]; v0.y += bias[1]; v0.z += bias[2]; v0.w += bias[3];
        v1.x += bias[4]; v1.y += bias[5]; v1.z += bias[6]; v1.w += bias[7];
        *(float4*)&g_xpre[m * GN + n0 + tx * 8]     = v0;
        *(float4*)&g_xpre[m * GN + n0 + tx * 8 + 4] = v1;
    }
}

// ============================================================
// Kernel 2: persistent bidirectional LSTM recurrence.
// 128 CTAs (64 per direction), 256 threads each, all co-resident.
// CTA cc of direction d owns h-indices [cc*8, cc*8+8) i.e. 32 gate rows.
// Per step:
//   compute phase : thread (w = k-chunk 0..7, b = lane 0..31) computes, for
//                   all 32 local gate rows j, the partial dot over k in
//                   [w*64, w*64+64) of W_hh[j][k]*h[b][k]; W from smem via
//                   broadcast LDS.128, h in registers (loaded from d_out of
//                   the previous step, or h0 at s=0).
//   update phase  : thread (hl = w, b) reduces 8 partials per gate, adds the
//                   prefetched x_pre value (biases folded in), applies the
//                   nonlinearities, carries c in a register, writes h into
//                   d_out (which doubles as the h exchange buffer).
//   grid barrier  : fence + atomic arrival counter + spin (monotonic target).
// ============================================================
#define REC_SMEM ((32 * 512 + 32 * 8 * 32) * 4)   // W slice 64KB + partials 32KB

__global__ void __launch_bounds__(256, 1) lstm_rec(
    const float* __restrict__ h0, const float* __restrict__ c0,
    const float* __restrict__ Whh, float* __restrict__ out,
    int write_states)
{
    extern __shared__ float smem[];
    float* sW = smem;                 // [32][512]
    float* sPart = smem + 32 * 512;   // [32][8][32]

    const int tid = threadIdx.x;
    const int cta = blockIdx.x;       // 0..127
    const int d = cta >> 6;           // direction
    const int cc = cta & 63;
    const int base = cc << 3;         // h index base (8 per CTA)
    const int w = tid >> 5;           // k-chunk / local h index
    const int b = tid & 31;           // batch

    // ---- load this CTA's W_hh slice: rows r = gate*8 + hl ----
    const float4* W4 = (const float4*)Whh;
    for (int i = tid; i < 32 * 128; i += 256) {
        int r = i >> 7;
        int k4 = i & 127;
        int grow = ((r >> 3) << 9) + base + (r & 7);     // gate*512 + base + hl
        ((float4*)sW)[r * 128 + k4] = W4[(size_t)(d * 2048 + grow) * 128 + k4];
    }

    float c = c0[(size_t)d * BB * HH + (size_t)b * HH + base + w];
    __syncthreads();

    for (int s = 0; s < TT; s++) {
        const int t = d ? (TT - 1 - s) : s;

        // prefetch gate inputs for the update phase (hides DRAM latency)
        const float* gp = g_xpre + ((size_t)(t * BB + b)) * GN + d * 2048 + base + w;
        float gi0 = gp[0], gi1 = gp[512], gi2 = gp[1024], gi3 = gp[1536];

        // ---- load h[b][w*64 .. w*64+63] into registers ----
        const float* hs;
        int hstr;
        if (s == 0) { hs = h0 + (size_t)d * BB * HH; hstr = HH; }
        else {
            int tp = d ? (t + 1) : (t - 1);
            hs = out + (size_t)tp * BB * 1024 + d * HH;
            hstr = 1024;
        }
        ulonglong2 h2[16];
        const ulonglong2* hp = (const ulonglong2*)(hs + (size_t)b * hstr + w * 64);
#pragma unroll
        for (int q = 0; q < 16; q++) h2[q] = hp[q];

        // ---- partial dot products ----
#pragma unroll 2
        for (int j = 0; j < 32; j++) {
            const ulonglong2* wp = (const ulonglong2*)(sW + j * 512 + w * 64);
            ull a0 = 0, a1 = 0, a2 = 0, a3 = 0;
#pragma unroll
            for (int q = 0; q < 16; q += 2) {
                ulonglong2 wv0 = wp[q];
                ulonglong2 wv1 = wp[q + 1];
                a0 = fma2(wv0.x, h2[q].x, a0);
                a1 = fma2(wv0.y, h2[q].y, a1);
                a2 = fma2(wv1.x, h2[q + 1].x, a2);
                a3 = fma2(wv1.y, h2[q + 1].y, a3);
            }
            ull aa = add2(add2(a0, a1), add2(a2, a3));
            float lo, hi;
            unpack2(aa, lo, hi);
            sPart[(j << 8) + (w << 5) + b] = lo + hi;
        }
        __syncthreads();

        // ---- update phase: thread (hl=w, b) ----
        float g4[4];
#pragma unroll
        for (int g = 0; g < 4; g++) {
            int j = g * 8 + w;
            const float* pp = sPart + (j << 8) + b;
            float sum = 0.f;
#pragma unroll
            for (int q = 0; q < 8; q++) sum += pp[q << 5];
            g4[g] = sum;
        }
        g4[0] += gi0; g4[1] += gi1; g4[2] += gi2; g4[3] += gi3;

        float ig = 1.f / (1.f + __expf(-g4[0]));
        float fg = 1.f / (1.f + __expf(-g4[1]));
        float gg = tanhf(g4[2]);
        float og = 1.f / (1.f + __expf(-g4[3]));
        c = fg * c + ig * gg;
        float h = og * tanhf(c);

        out[(size_t)t * BB * 1024 + (size_t)b * 1024 + d * HH + base + w] = h;
        if (s == TT - 1 && write_states) {
            size_t so = (size_t)16777216;  // T*B*2H
            out[so + ((size_t)d * BB + b) * HH + base + w] = h;               // h_out
            out[so + 2 * BB * HH + ((size_t)d * BB + b) * HH + base + w] = c; // c_out
        }

        // ---- grid barrier (skip after last step) ----
        __syncthreads();
        if (s < TT - 1) {
            if (tid == 0) {
                __threadfence();
                atomicAdd(&g_bar, 1u);
                unsigned tgt = (unsigned)(s + 1) * 128u;
                while (*(volatile unsigned*)&g_bar < tgt) __nanosleep(32);
                __threadfence();
            }
            __syncthreads();
        }
    }
}

// ============================================================
// launch
// ============================================================
extern "C" void kernel_launch(void* const* d_in, const int* in_sizes, int n_in,
                              void* d_out, int out_size)
{
    const float* x    = (const float*)d_in[0];   // [512,32,512]
    const float* h0   = (const float*)d_in[1];   // [2,32,512]
    const float* c0   = (const float*)d_in[2];   // [2,32,512]
    const float* W_ih = (const float*)d_in[3];   // [2,2048,512]
    const float* b_ih = (const float*)d_in[4];   // [2,2048]
    const float* W_hh = (const float*)d_in[5];   // [2,2048,512]
    const float* b_hh = (const float*)d_in[6];   // [2,2048]
    float* out = (float*)d_out;

    int write_states = (out_size >= 16777216 + 2 * 2 * BB * HH) ? 1 : 0;

    dim3 ggrid(GN / BN, GM / BM);   // (32, 128)
    gemm_xpre<<<ggrid, 256>>>(x, W_ih, b_ih, b_hh);

    static int smem_set = 0;
    (void)smem_set;
    cudaFuncSetAttribute(lstm_rec, cudaFuncAttributeMaxDynamicSharedMemorySize, REC_SMEM);
    lstm_rec<<<128, 256, REC_SMEM>>>(h0, c0, W_hh, out, write_states);
}

// round 12
// speedup vs baseline: 1.1578x; 1.1578x over previous
#include <cuda_runtime.h>
#include <cuda_bf16.h>

typedef unsigned long long ull;

// ---------------- problem constants ----------------
#define TT 512
#define BB 32
#define HH 512
#define GM 16384          // T*B
#define GN 4096           // 2 dirs * 4H
#define GK 512            // D (= H)

// ---------------- scratch ----------------
__device__ float g_xpre[(size_t)GM * GN];   // precomputed input gates (+ both biases)
__device__ unsigned int g_arr[2];           // per-direction arrival counters
__device__ unsigned int g_gen[2];           // per-direction generation flags

// ---------------- f32x2 helpers ----------------
__device__ __forceinline__ ull pack2(float lo, float hi) {
    ull r; asm("mov.b64 %0, {%1, %2};" : "=l"(r) : "f"(lo), "f"(hi)); return r;
}
__device__ __forceinline__ void unpack2(ull v, float& lo, float& hi) {
    asm("mov.b64 {%0, %1}, %2;" : "=f"(lo), "=f"(hi) : "l"(v));
}
__device__ __forceinline__ ull fma2(ull a, ull b, ull c) {
    ull d; asm("fma.rn.f32x2 %0, %1, %2, %3;" : "=l"(d) : "l"(a), "l"(b), "l"(c)); return d;
}
__device__ __forceinline__ ull add2(ull a, ull b) {
    ull d; asm("add.rn.f32x2 %0, %1, %2;" : "=l"(d) : "l"(a), "l"(b)); return d;
}

// ============================================================
// Kernel 1: x_pre GEMM.  C[m][n] = A[m][:] . W[n][:] + bih[n] + bhh[n]
// ============================================================
#define BM 128
#define BN 128
#define BK 16

__global__ void __launch_bounds__(256, 2) gemm_xpre(
    const float* __restrict__ A, const float* __restrict__ W,
    const float* __restrict__ bih, const float* __restrict__ bhh)
{
    if (blockIdx.x == 0 && blockIdx.y == 0 && threadIdx.x == 0) {
        g_arr[0] = 0; g_arr[1] = 0; g_gen[0] = 0; g_gen[1] = 0;
    }

    __shared__ float As[2][BK][BM];
    __shared__ float Bs[2][BK][BN];

    const int tid = threadIdx.x;
    const int m0 = blockIdx.y * BM;
    const int n0 = blockIdx.x * BN;

    const int lr = tid >> 2;           // 0..63
    const int lk = (tid & 3) << 2;     // 0,4,8,12
    const int lk4 = tid & 3;

    const float4* A4 = (const float4*)A;
    const float4* W4 = (const float4*)W;

    const int ty = tid >> 4;
    const int tx = tid & 15;

    ull acc[8][4];
#pragma unroll
    for (int i = 0; i < 8; i++)
#pragma unroll
        for (int j = 0; j < 4; j++) acc[i][j] = 0ull;

    {
        int ak = lk4;
        float4 a0 = A4[(size_t)(m0 + lr) * 128 + ak];
        float4 a1 = A4[(size_t)(m0 + lr + 64) * 128 + ak];
        float4 b0 = W4[(size_t)(n0 + lr) * 128 + ak];
        float4 b1 = W4[(size_t)(n0 + lr + 64) * 128 + ak];
        As[0][lk + 0][lr] = a0.x; As[0][lk + 1][lr] = a0.y;
        As[0][lk + 2][lr] = a0.z; As[0][lk + 3][lr] = a0.w;
        As[0][lk + 0][lr + 64] = a1.x; As[0][lk + 1][lr + 64] = a1.y;
        As[0][lk + 2][lr + 64] = a1.z; As[0][lk + 3][lr + 64] = a1.w;
        Bs[0][lk + 0][lr] = b0.x; Bs[0][lk + 1][lr] = b0.y;
        Bs[0][lk + 2][lr] = b0.z; Bs[0][lk + 3][lr] = b0.w;
        Bs[0][lk + 0][lr + 64] = b1.x; Bs[0][lk + 1][lr + 64] = b1.y;
        Bs[0][lk + 2][lr + 64] = b1.z; Bs[0][lk + 3][lr + 64] = b1.w;
    }
    __syncthreads();

    int bf = 0;
    const int NKT = GK / BK;
    float4 ra0, ra1, rb0, rb1;

    for (int kt = 0; kt < NKT; kt++) {
        if (kt < NKT - 1) {
            int ak = (kt + 1) * 4 + lk4;
            ra0 = A4[(size_t)(m0 + lr) * 128 + ak];
            ra1 = A4[(size_t)(m0 + lr + 64) * 128 + ak];
            rb0 = W4[(size_t)(n0 + lr) * 128 + ak];
            rb1 = W4[(size_t)(n0 + lr + 64) * 128 + ak];
        }
#pragma unroll
        for (int k = 0; k < BK; k++) {
            float4 a0 = *(const float4*)&As[bf][k][ty * 8];
            float4 a1 = *(const float4*)&As[bf][k][ty * 8 + 4];
            ulonglong2 bA = *(const ulonglong2*)&Bs[bf][k][tx * 8];
            ulonglong2 bB = *(const ulonglong2*)&Bs[bf][k][tx * 8 + 4];
            ull bb0 = bA.x, bb1 = bA.y, bb2 = bB.x, bb3 = bB.y;
            float av[8] = {a0.x, a0.y, a0.z, a0.w, a1.x, a1.y, a1.z, a1.w};
#pragma unroll
            for (int i = 0; i < 8; i++) {
                ull ap = pack2(av[i], av[i]);
                acc[i][0] = fma2(ap, bb0, acc[i][0]);
                acc[i][1] = fma2(ap, bb1, acc[i][1]);
                acc[i][2] = fma2(ap, bb2, acc[i][2]);
                acc[i][3] = fma2(ap, bb3, acc[i][3]);
            }
        }
        if (kt < NKT - 1) {
            int nb = bf ^ 1;
            As[nb][lk + 0][lr] = ra0.x; As[nb][lk + 1][lr] = ra0.y;
            As[nb][lk + 2][lr] = ra0.z; As[nb][lk + 3][lr] = ra0.w;
            As[nb][lk + 0][lr + 64] = ra1.x; As[nb][lk + 1][lr + 64] = ra1.y;
            As[nb][lk + 2][lr + 64] = ra1.z; As[nb][lk + 3][lr + 64] = ra1.w;
            Bs[nb][lk + 0][lr] = rb0.x; Bs[nb][lk + 1][lr] = rb0.y;
            Bs[nb][lk + 2][lr] = rb0.z; Bs[nb][lk + 3][lr] = rb0.w;
            Bs[nb][lk + 0][lr + 64] = rb1.x; Bs[nb][lk + 1][lr + 64] = rb1.y;
            Bs[nb][lk + 2][lr + 64] = rb1.z; Bs[nb][lk + 3][lr + 64] = rb1.w;
            __syncthreads();
            bf = nb;
        }
    }

    float bias[8];
#pragma unroll
    for (int j = 0; j < 8; j++) {
        int n = n0 + tx * 8 + j;
        bias[j] = bih[n] + bhh[n];
    }
#pragma unroll
    for (int i = 0; i < 8; i++) {
        size_t m = (size_t)(m0 + ty * 8 + i);
        float4 v0, v1;
        unpack2(acc[i][0], v0.x, v0.y);
        unpack2(acc[i][1], v0.z, v0.w);
        unpack2(acc[i][2], v1.x, v1.y);
        unpack2(acc[i][3], v1.z, v1.w);
        v0.x += bias[0]; v0.y += bias[1]; v0.z += bias[2]; v0.w += bias[3];
        v1.x += bias[4]; v1.y += bias[5]; v1.z += bias[6]; v1.w += bias[7];
        *(float4*)&g_xpre[m * GN + n0 + tx * 8]     = v0;
        *(float4*)&g_xpre[m * GN + n0 + tx * 8 + 4] = v1;
    }
}

// ============================================================
// Kernel 2: persistent bidirectional LSTM recurrence.
// 128 CTAs (64/direction), 256 threads. All global traffic per step is
// coalesced through shared-memory staging buffers:
//   hT  [32][516]  : previous h, loaded as 16 float4/thread (coalesced)
//   sGI [32][33]   : x_pre gate inputs for this step (prefetched 1 step ahead)
//   sHO [32][9]    : h output, written back coalesced
// Compute phase unchanged: W_hh rows broadcast from smem (LDS.128 uniform),
// h in registers, 4 independent f32x2 accumulator chains.
// Per-direction grid barrier (directions are independent).
// ============================================================
#define HT_P 516
#define OFF_W    0
#define OFF_HT   16384                       // 32*516 = 16512 floats
#define OFF_PART (16384 + 32 * HT_P)         // 8192 floats
#define OFF_GI   (OFF_PART + 8192)           // 32*33 = 1056 floats
#define OFF_HO   (OFF_GI + 32 * 33)          // 32*9  = 288 floats
#define REC_FLOATS (OFF_HO + 32 * 9)
#define REC_SMEM (REC_FLOATS * 4)            // 169728 bytes

__global__ void __launch_bounds__(256, 1) lstm_rec(
    const float* __restrict__ h0, const float* __restrict__ c0,
    const float* __restrict__ Whh, float* __restrict__ out,
    int write_states)
{
    extern __shared__ float sm[];
    float* sW    = sm + OFF_W;      // [32][512]
    float* hT    = sm + OFF_HT;     // [32][516]
    float* sPart = sm + OFF_PART;   // [32][8][32]
    float* sGI   = sm + OFF_GI;     // [32][33] (4 gates x 8 w, padded)
    float* sHO   = sm + OFF_HO;     // [32][9]

    const int tid = threadIdx.x;
    const int cta = blockIdx.x;       // 0..127
    const int d = cta >> 6;           // direction
    const int cc = cta & 63;
    const int base = cc << 3;         // h index base (8 per CTA)
    const int w = tid >> 5;           // k-chunk / local h index (0..7)
    const int b = tid & 31;           // batch

    // ---- load this CTA's W_hh slice: rows r = gate*8 + hl ----
    const float4* W4 = (const float4*)Whh;
    for (int i = tid; i < 32 * 128; i += 256) {
        int r = i >> 7;
        int k4 = i & 127;
        int grow = ((r >> 3) << 9) + base + (r & 7);     // gate*512 + base + hl
        ((float4*)sW)[r * 128 + k4] = W4[(size_t)(d * 2048 + grow) * 128 + k4];
    }

    float c = c0[(size_t)d * BB * HH + (size_t)b * HH + base + w];

    // ---- prologue: prefetch gate inputs for step 0 (coalesced) ----
    float gi[4];
    {
        int t0 = d ? (TT - 1) : 0;
#pragma unroll
        for (int i = 0; i < 4; i++) {
            int idx = tid + (i << 8);
            int bb2 = idx >> 5, g = (idx >> 3) & 3, wi = idx & 7;
            gi[i] = g_xpre[(size_t)(t0 * BB + bb2) * GN + d * 2048 + g * 512 + base + wi];
        }
    }
    __syncthreads();

    for (int s = 0; s < TT; s++) {
        const int t = d ? (TT - 1 - s) : s;

        // ---- (a) deposit prefetched gate inputs into sGI ----
#pragma unroll
        for (int i = 0; i < 4; i++) {
            int idx = tid + (i << 8);
            int bb2 = idx >> 5, g = (idx >> 3) & 3, wi = idx & 7;
            sGI[bb2 * 33 + g * 8 + wi] = gi[i];
        }

        // ---- (b) stage previous h into hT (coalesced LDG + conflict-free STS) ----
        {
            const float* hsrc;
            int hstr4;
            if (s == 0) { hsrc = h0 + (size_t)d * BB * HH; hstr4 = HH >> 2; }
            else {
                int tp = d ? (t + 1) : (t - 1);
                hsrc = out + (size_t)tp * BB * 1024 + d * HH;
                hstr4 = 1024 >> 2;
            }
            const float4* s4 = (const float4*)hsrc;
#pragma unroll
            for (int i = 0; i < 16; i++) {
                int idx = tid + (i << 8);       // 0..4095
                int bb2 = idx >> 7;             // batch row
                int kq  = idx & 127;            // float4 within row
                float4 v = s4[(size_t)bb2 * hstr4 + kq];
                *(float4*)&hT[bb2 * HT_P + (kq << 2)] = v;
            }
        }

        // ---- (c) prefetch gate inputs for NEXT step (latency hidden by compute) ----
        if (s < TT - 1) {
            int tn = d ? (TT - 2 - s) : (s + 1);
#pragma unroll
            for (int i = 0; i < 4; i++) {
                int idx = tid + (i << 8);
                int bb2 = idx >> 5, g = (idx >> 3) & 3, wi = idx & 7;
                gi[i] = g_xpre[(size_t)(tn * BB + bb2) * GN + d * 2048 + g * 512 + base + wi];
            }
        }
        __syncthreads();

        // ---- (e) compute: h from smem, W broadcast from smem ----
        ulonglong2 h2[16];
        {
            const ulonglong2* hp = (const ulonglong2*)&hT[b * HT_P + (w << 6)];
#pragma unroll
            for (int q = 0; q < 16; q++) h2[q] = hp[q];
        }

#pragma unroll 4
        for (int j = 0; j < 32; j++) {
            const ulonglong2* wp = (const ulonglong2*)(sW + j * 512 + (w << 6));
            ull a0 = 0, a1 = 0, a2 = 0, a3 = 0;
#pragma unroll
            for (int q = 0; q < 16; q += 2) {
                ulonglong2 wv0 = wp[q];
                ulonglong2 wv1 = wp[q + 1];
                a0 = fma2(wv0.x, h2[q].x, a0);
                a1 = fma2(wv0.y, h2[q].y, a1);
                a2 = fma2(wv1.x, h2[q + 1].x, a2);
                a3 = fma2(wv1.y, h2[q + 1].y, a3);
            }
            ull aa = add2(add2(a0, a1), add2(a2, a3));
            float lo, hi;
            unpack2(aa, lo, hi);
            sPart[(j << 8) + (w << 5) + b] = lo + hi;
        }
        __syncthreads();

        // ---- (g) update phase: thread (hl=w, b) ----
        float g4[4];
#pragma unroll
        for (int g = 0; g < 4; g++) {
            int j = g * 8 + w;
            const float* pp = sPart + (j << 8) + b;
            float sum = 0.f;
#pragma unroll
            for (int q = 0; q < 8; q++) sum += pp[q << 5];
            g4[g] = sum + sGI[b * 33 + g * 8 + w];
        }

        float ig = 1.f / (1.f + __expf(-g4[0]));
        float fg = 1.f / (1.f + __expf(-g4[1]));
        float gg = tanhf(g4[2]);
        float og = 1.f / (1.f + __expf(-g4[3]));
        c = fg * c + ig * gg;
        float h = og * tanhf(c);

        sHO[b * 9 + w] = h;
        if (s == TT - 1 && write_states) {
            size_t so = (size_t)16777216;  // T*B*2H
            out[so + ((size_t)d * BB + b) * HH + base + w] = h;               // h_out
            out[so + 2 * BB * HH + ((size_t)d * BB + b) * HH + base + w] = c; // c_out
        }
        __syncthreads();

        // ---- (j) coalesced h writeback ----
        {
            int bb2 = tid >> 3, wi = tid & 7;
            out[(size_t)t * BB * 1024 + (size_t)bb2 * 1024 + d * HH + base + wi] =
                sHO[bb2 * 9 + wi];
        }

        // ---- (k) per-direction grid barrier ----
        if (s < TT - 1) {
            __syncthreads();
            if (tid == 0) {
                __threadfence();
                unsigned old = atomicAdd(&g_arr[d], 1u);
                if (old == (unsigned)s * 64u + 63u) {
                    atomicExch(&g_gen[d], (unsigned)(s + 1));
                } else {
                    while (((volatile unsigned*)g_gen)[d] < (unsigned)(s + 1)) { }
                }
                __threadfence();
            }
            __syncthreads();
        }
    }
}

// ============================================================
// launch
// ============================================================
extern "C" void kernel_launch(void* const* d_in, const int* in_sizes, int n_in,
                              void* d_out, int out_size)
{
    const float* x    = (const float*)d_in[0];   // [512,32,512]
    const float* h0   = (const float*)d_in[1];   // [2,32,512]
    const float* c0   = (const float*)d_in[2];   // [2,32,512]
    const float* W_ih = (const float*)d_in[3];   // [2,2048,512]
    const float* b_ih = (const float*)d_in[4];   // [2,2048]
    const float* W_hh = (const float*)d_in[5];   // [2,2048,512]
    const float* b_hh = (const float*)d_in[6];   // [2,2048]
    float* out = (float*)d_out;

    int write_states = (out_size >= 16777216 + 2 * 2 * BB * HH) ? 1 : 0;

    dim3 ggrid(GN / BN, GM / BM);   // (32, 128)
    gemm_xpre<<<ggrid, 256>>>(x, W_ih, b_ih, b_hh);

    cudaFuncSetAttribute(lstm_rec, cudaFuncAttributeMaxDynamicSharedMemorySize, REC_SMEM);
    lstm_rec<<<128, 256, REC_SMEM>>>(h0, c0, W_hh, out, write_states);
}